// round 2
// baseline (speedup 1.0000x reference)
#include <cuda_runtime.h>

// Problem constants (fixed by the reference: N=16384, D=2, H=128)
constexpr int N_ROWS = 16384;
constexpr int H      = 128;
constexpr int NHi    = N_ROWS * H;          // 2,097,152 floats per [N,H] tensor

constexpr int BLOCKS  = 1024;
constexpr int THREADS = 256;
constexpr int WPB     = 8;                          // warps per block
constexpr int TOTAL_WARPS   = BLOCKS * WPB;         // 8192
constexpr int ROWS_PER_WARP = N_ROWS / TOTAL_WARPS; // 2

// Scratch (allocation-free: __device__ globals)
__device__ float g_ysum[H];      // sum_y bi_dec[y]  (accumulated via atomics)
__device__ float g_scalars[3];   // [0]=sum||bi_dec||^2  [1]=sum diag  [2]=nce

__device__ __forceinline__ float warp_sum(float v) {
    #pragma unroll
    for (int o = 16; o > 0; o >>= 1) v += __shfl_down_sync(0xffffffffu, v, o);
    return v;
}

// K0: reset accumulators (graph replays -> must re-zero every run)
__global__ void zero_kernel() {
    const int t = threadIdx.x;
    if (t < H) g_ysum[t] = 0.0f;
    if (t >= H && t < H + 3) g_scalars[t - H] = 0.0f;
}

// K1 (dec pass): bi_dec = sum over direction axis of dec; store to out region 3.
// Accumulate Ysum (per-column sum of bi_dec) and Synorm = sum ||bi_dec||^2.
// One warp per row (2 rows/warp); lane owns columns [4*lane, 4*lane+4).
__global__ __launch_bounds__(THREADS) void dec_kernel(
    const float* __restrict__ dec, float* __restrict__ out)
{
    const int tid   = threadIdx.x;
    const int lane  = tid & 31;
    const int w     = tid >> 5;
    const int gwarp = blockIdx.x * WPB + w;

    float ys0 = 0.f, ys1 = 0.f, ys2 = 0.f, ys3 = 0.f;
    float ynorm = 0.f;

    #pragma unroll
    for (int i = 0; i < ROWS_PER_WARP; i++) {
        const int r = gwarp + i * TOTAL_WARPS;
        // row r of dec = 256 floats = 64 float4; direction halves at +0 / +32
        const float4 c = __ldg((const float4*)dec + r * 64 + lane);
        const float4 d = __ldg((const float4*)dec + r * 64 + 32 + lane);
        float4 f; f.x = c.x + d.x; f.y = c.y + d.y; f.z = c.z + d.z; f.w = c.w + d.w;

        ((float4*)out)[NHi / 2 + r * 32 + lane] = f;   // bi_dec region

        ys0 += f.x; ys1 += f.y; ys2 += f.z; ys3 += f.w;
        ynorm += f.x * f.x + f.y * f.y + f.z * f.z + f.w * f.w;
    }
    ynorm = warp_sum(ynorm);

    __shared__ float s_ys[WPB][H];
    __shared__ float s_yn[WPB];
    s_ys[w][4 * lane + 0] = ys0;
    s_ys[w][4 * lane + 1] = ys1;
    s_ys[w][4 * lane + 2] = ys2;
    s_ys[w][4 * lane + 3] = ys3;
    if (lane == 0) s_yn[w] = ynorm;
    __syncthreads();

    if (tid < H) {
        float s = 0.f;
        #pragma unroll
        for (int ww = 0; ww < WPB; ww++) s += s_ys[ww][tid];
        atomicAdd(&g_ysum[tid], s);
    } else if (tid == H) {
        float yn = 0.f;
        #pragma unroll
        for (int ww = 0; ww < WPB; ww++) yn += s_yn[ww];
        atomicAdd(&g_scalars[0], yn);
    }
}

// K2 (enc pass, fully fused): bi_enc = sum of enc directions; store twice.
// Per row, one combined reduction:
//   q = sum_cols( -N*e^2 + 2*e*Ysum + 10*(e-f)^2 )
//   row_loss = 5 - Synorm + q ;  nce += relu(row_loss)
// Also accumulates sum diag = sum (e-f)^2 for diagonal_loss.
// bi_dec is re-read from out (written by K1 -> L2-resident).
__global__ __launch_bounds__(THREADS) void enc_kernel(
    const float* __restrict__ enc, float* __restrict__ out)
{
    const int tid   = threadIdx.x;
    const int lane  = tid & 31;
    const int w     = tid >> 5;
    const int gwarp = blockIdx.x * WPB + w;

    const float4 ys = ((const float4*)g_ysum)[lane];
    const float synorm = g_scalars[0];

    float dg_acc  = 0.f;   // per-lane sum of diag contributions
    float nce_acc = 0.f;   // valid on lane 0

    #pragma unroll
    for (int i = 0; i < ROWS_PER_WARP; i++) {
        const int r = gwarp + i * TOTAL_WARPS;
        const float4 a = __ldg((const float4*)enc + r * 64 + lane);
        const float4 b = __ldg((const float4*)enc + r * 64 + 32 + lane);
        const float4 f = __ldg((const float4*)out + NHi / 2 + r * 32 + lane);

        float4 e; e.x = a.x + b.x; e.y = a.y + b.y; e.z = a.z + b.z; e.w = a.w + b.w;

        ((float4*)out)[          r * 32 + lane] = e;   // bi_enc
        ((float4*)out)[NHi / 4 + r * 32 + lane] = e;   // bi_enc (again)

        const float gx = e.x - f.x, gy = e.y - f.y, gz = e.z - f.z, gw = e.w - f.w;
        const float dgl = gx * gx + gy * gy + gz * gz + gw * gw;
        const float en  = e.x * e.x + e.y * e.y + e.z * e.z + e.w * e.w;
        const float dp  = e.x * ys.x + e.y * ys.y + e.z * ys.z + e.w * ys.w;

        dg_acc += dgl;
        float q = fmaf(-(float)N_ROWS, en, fmaf(2.0f, dp, 10.0f * dgl));
        q = warp_sum(q);
        if (lane == 0) nce_acc += fmaxf(5.0f - synorm + q, 0.0f);
    }
    dg_acc = warp_sum(dg_acc);

    __shared__ float s_nce[WPB];
    __shared__ float s_dg[WPB];
    if (lane == 0) { s_nce[w] = nce_acc; s_dg[w] = dg_acc; }
    __syncthreads();
    if (tid == 0) {
        float tn = 0.f, td = 0.f;
        #pragma unroll
        for (int ww = 0; ww < WPB; ww++) { tn += s_nce[ww]; td += s_dg[ww]; }
        atomicAdd(&g_scalars[2], tn);
        atomicAdd(&g_scalars[1], td);
    }
}

// K3: write the two scalar outputs.
__global__ void finalize_kernel(float* __restrict__ out) {
    out[3 * NHi]     = g_scalars[2];                    // nce_loss
    out[3 * NHi + 1] = -g_scalars[1] / (float)N_ROWS;   // diagonal_loss
}

extern "C" void kernel_launch(void* const* d_in, const int* in_sizes, int n_in,
                              void* d_out, int out_size) {
    const float* enc = (const float*)d_in[0];
    const float* dec = (const float*)d_in[1];
    float* out = (float*)d_out;

    zero_kernel<<<1, H + 32>>>();
    dec_kernel<<<BLOCKS, THREADS>>>(dec, out);
    enc_kernel<<<BLOCKS, THREADS>>>(enc, out);
    finalize_kernel<<<1, 1>>>(out);
}

// round 3
// speedup vs baseline: 1.0118x; 1.0118x over previous
#include <cuda_runtime.h>

// Problem constants (fixed by the reference: N=16384, D=2, H=128)
constexpr int N_ROWS = 16384;
constexpr int H      = 128;
constexpr int NHi    = N_ROWS * H;          // floats per [N,H] tensor

constexpr int BLOCKS  = 512;
constexpr int THREADS = 256;
constexpr int WPB     = 8;                           // warps per block
constexpr int TOTAL_WARPS   = BLOCKS * WPB;          // 4096
constexpr int ROWS_PER_WARP = N_ROWS / TOTAL_WARPS;  // 4

// Scratch (allocation-free __device__ globals). Zero at module load; the
// kernel re-zeros them at its own tail so every graph replay starts clean.
__device__ float    g_ysum[H];     // sum_y bi_dec[y][c]
__device__ float    g_scalars[3];  // [0]=Synorm  [1]=sum diag  [2]=nce
__device__ unsigned g_count;       // barrier arrival counter (returns to 0)
__device__ unsigned g_gen;         // barrier generation (monotonic, may wrap)

__device__ __forceinline__ float warp_sum(float v) {
    #pragma unroll
    for (int o = 16; o > 0; o >>= 1) v += __shfl_down_sync(0xffffffffu, v, o);
    return v;
}

// Software grid barrier. Safe because all BLOCKS are co-resident
// (512 <= 4 blocks/SM * 152 SMs guaranteed by __launch_bounds__).
__device__ __forceinline__ void grid_barrier() {
    __syncthreads();
    if (threadIdx.x == 0) {
        __threadfence();
        volatile unsigned* genp = &g_gen;
        const unsigned gen = *genp;                 // read BEFORE arriving
        if (atomicAdd(&g_count, 1u) == BLOCKS - 1) {
            atomicExch(&g_count, 0u);
            __threadfence();
            atomicAdd(&g_gen, 1u);                  // release
        } else {
            while (*genp == gen) { __nanosleep(64); }
        }
        __threadfence();
    }
    __syncthreads();
}

__global__ __launch_bounds__(THREADS, 4) void fused_kernel(
    const float* __restrict__ enc, const float* __restrict__ dec,
    float* __restrict__ out)
{
    const int tid   = threadIdx.x;
    const int lane  = tid & 31;
    const int w     = tid >> 5;
    const int gwarp = blockIdx.x * WPB + w;

    __shared__ float s_ys[WPB][H];
    __shared__ float s_sc[WPB][2];
    __shared__ float s_nce[WPB];

    // ---------------- Phase 1: stream everything once ----------------
    float4 e_reg[ROWS_PER_WARP];    // bi_enc stays in registers
    float  h_reg[ROWS_PER_WARP];    // per-lane: -N*e^2 + 10*(e-f)^2 partial
    float ys0 = 0.f, ys1 = 0.f, ys2 = 0.f, ys3 = 0.f;
    float ynorm = 0.f, dgsum = 0.f;

    #pragma unroll
    for (int i = 0; i < ROWS_PER_WARP; i++) {
        const int r = gwarp + i * TOTAL_WARPS;
        // row r = 256 floats = 64 float4; direction halves at +0 / +32
        const float4 a = __ldg((const float4*)enc + r * 64 + lane);
        const float4 b = __ldg((const float4*)enc + r * 64 + 32 + lane);
        const float4 c = __ldg((const float4*)dec + r * 64 + lane);
        const float4 d = __ldg((const float4*)dec + r * 64 + 32 + lane);

        float4 e; e.x = a.x + b.x; e.y = a.y + b.y; e.z = a.z + b.z; e.w = a.w + b.w;
        float4 f; f.x = c.x + d.x; f.y = c.y + d.y; f.z = c.z + d.z; f.w = c.w + d.w;

        ((float4*)out)[          r * 32 + lane] = e;   // bi_enc
        ((float4*)out)[NHi / 4 + r * 32 + lane] = e;   // bi_enc (again)
        ((float4*)out)[NHi / 2 + r * 32 + lane] = f;   // bi_dec

        ys0 += f.x; ys1 += f.y; ys2 += f.z; ys3 += f.w;
        ynorm += f.x * f.x + f.y * f.y + f.z * f.z + f.w * f.w;

        const float en  = e.x * e.x + e.y * e.y + e.z * e.z + e.w * e.w;
        const float gx = e.x - f.x, gy = e.y - f.y, gz = e.z - f.z, gw = e.w - f.w;
        const float dgl = gx * gx + gy * gy + gz * gz + gw * gw;

        dgsum   += dgl;
        h_reg[i] = fmaf(-(float)N_ROWS, en, 10.0f * dgl);
        e_reg[i] = e;
    }
    ynorm = warp_sum(ynorm);
    dgsum = warp_sum(dgsum);

    s_ys[w][4 * lane + 0] = ys0;
    s_ys[w][4 * lane + 1] = ys1;
    s_ys[w][4 * lane + 2] = ys2;
    s_ys[w][4 * lane + 3] = ys3;
    if (lane == 0) { s_sc[w][0] = ynorm; s_sc[w][1] = dgsum; }
    __syncthreads();

    if (tid < H) {
        float s = 0.f;
        #pragma unroll
        for (int ww = 0; ww < WPB; ww++) s += s_ys[ww][tid];
        atomicAdd(&g_ysum[tid], s);
    } else if (tid == H) {
        float yn = 0.f, ds = 0.f;
        #pragma unroll
        for (int ww = 0; ww < WPB; ww++) { yn += s_sc[ww][0]; ds += s_sc[ww][1]; }
        atomicAdd(&g_scalars[0], yn);
        atomicAdd(&g_scalars[1], ds);
    }

    grid_barrier();   // Ysum / Synorm now complete

    // ---------------- Phase 2: nce from register-resident e ----------------
    const float4 ys = __ldcg((const float4*)g_ysum + lane);   // L2, not stale L1
    const float synorm = __ldcg(&g_scalars[0]);

    float nce_acc = 0.f;
    #pragma unroll
    for (int i = 0; i < ROWS_PER_WARP; i++) {
        const float4 e = e_reg[i];
        const float dp = e.x * ys.x + e.y * ys.y + e.z * ys.z + e.w * ys.w;
        float q = fmaf(2.0f, dp, h_reg[i]);
        q = warp_sum(q);
        if (lane == 0) nce_acc += fmaxf(5.0f - synorm + q, 0.0f);
    }

    if (lane == 0) s_nce[w] = nce_acc;
    __syncthreads();
    if (tid == 0) {
        float tn = 0.f;
        #pragma unroll
        for (int ww = 0; ww < WPB; ww++) tn += s_nce[ww];
        atomicAdd(&g_scalars[2], tn);
    }

    grid_barrier();   // all scalar accumulation complete

    // ---------------- Tail: block 0 writes scalars, re-zeros state ----------
    if (blockIdx.x == 0) {
        if (tid == 0) {
            out[3 * NHi]     = __ldcg(&g_scalars[2]);                    // nce_loss
            out[3 * NHi + 1] = -__ldcg(&g_scalars[1]) / (float)N_ROWS;   // diagonal_loss
        }
        __syncthreads();   // reads above complete before re-zeroing
        if (tid < H) g_ysum[tid] = 0.0f;
        if (tid >= H && tid < H + 3) g_scalars[tid - H] = 0.0f;
    }
}

extern "C" void kernel_launch(void* const* d_in, const int* in_sizes, int n_in,
                              void* d_out, int out_size) {
    const float* enc = (const float*)d_in[0];
    const float* dec = (const float*)d_in[1];
    float* out = (float*)d_out;

    fused_kernel<<<BLOCKS, THREADS>>>(enc, dec, out);
}